// round 8
// baseline (speedup 1.0000x reference)
#include <cuda_runtime.h>
#include <stdint.h>

#define N_NODES 10000
#define N_EDGES 320000
#define N_PAIRS 2048
#define IN_CH   128
#define HIDDEN  512

// 1-bit presence bitmap: row stride 320 u32 (10240 bits >= 10000).
// 12.8 MB total -> fully L2-resident.
#define ROW_WB  320
#define ROW_B4  80               // uint4 chunks per bitmap row
#define BMP_U4  ((size_t)N_NODES * ROW_WB / 4)   // 800k uint4

// Exception hash for multiplicity > 1 (expected ~1k entries)
#define HSIZE   32768
#define HMASK   (HSIZE - 1)

__device__ __align__(16) unsigned int g_B[(size_t)N_NODES * ROW_WB];  // presence bits
__device__ __align__(16) unsigned int g_hk[HSIZE];   // key+1, 0 = empty
__device__ __align__(16) unsigned int g_hc[HSIZE];   // extra count (c-1)
// xs features: [N_PAIRS][2*IN_CH]
__device__ __align__(16) float g_XS[N_PAIRS * 2 * IN_CH];

// ---------------------------------------------------------------------------
// Inline index-dtype detection (warp-uniform)
// ---------------------------------------------------------------------------
__device__ __forceinline__ int detect64(const void* p) {
    const unsigned int* p32 = (const unsigned int*)p;
    int lane = threadIdx.x & 31;
    bool all0 = (p32[2 * lane + 1] | p32[2 * (lane + 32) + 1]) == 0u;
    return __ballot_sync(0xFFFFFFFFu, all0) == 0xFFFFFFFFu;
}
__device__ __forceinline__ long long load_idx(const void* p, int is64, long long j) {
    if (is64) return ((const long long*)p)[j];
    return (long long)((const int*)p)[j];
}

// ---------------------------------------------------------------------------
// Exception hash (open addressing, linear probe)
// ---------------------------------------------------------------------------
__device__ __forceinline__ void hash_add(unsigned key) {
    unsigned idx = (key * 2654435761u) & HMASK;
    for (;;) {
        unsigned cur = g_hk[idx];
        if (cur == key + 1u) { atomicAdd(&g_hc[idx], 1u); return; }
        if (cur == 0u) {
            unsigned old = atomicCAS(&g_hk[idx], 0u, key + 1u);
            if (old == 0u || old == key + 1u) { atomicAdd(&g_hc[idx], 1u); return; }
        }
        idx = (idx + 1u) & HMASK;
    }
}
__device__ __forceinline__ unsigned hash_get(unsigned key) {
    unsigned idx = (key * 2654435761u) & HMASK;
    for (;;) {
        unsigned cur = g_hk[idx];
        if (cur == 0u) return 0u;
        if (cur == key + 1u) return g_hc[idx];
        idx = (idx + 1u) & HMASK;
    }
}

// ---------------------------------------------------------------------------
// 1) Scatter: set presence bits; duplicates go to the exception hash
// ---------------------------------------------------------------------------
__global__ void scatter_kernel(const void* __restrict__ ei) {
    int is64 = detect64(ei);
    int e = blockIdx.x * blockDim.x + threadIdx.x;
    if (e >= N_EDGES) return;
    long long s = load_idx(ei, is64, e);
    long long d = load_idx(ei, is64, (long long)N_EDGES + e);
    unsigned bd = 1u << (d & 31);
    unsigned bs = 1u << (s & 31);
    unsigned o1 = atomicOr(&g_B[(size_t)s * ROW_WB + (size_t)(d >> 5)], bd);
    unsigned o2 = atomicOr(&g_B[(size_t)d * ROW_WB + (size_t)(s >> 5)], bs);
    if (o1 & bd) hash_add((unsigned)(s * 16384 + d));
    if (o2 & bs) hash_add((unsigned)(d * 16384 + s));
}

// ---------------------------------------------------------------------------
// 2) Per-pair: intersect bitmap rows; exception lookup only at hits.
//    Also initializes out[b] = b2[0] (block b owns pair b).
// ---------------------------------------------------------------------------
__global__ void pairs_kernel(const void* __restrict__ tar,
                             const float* __restrict__ x,
                             const float* __restrict__ b2,
                             float* __restrict__ out) {
    __shared__ int   s_n[512];
    __shared__ float s_w[512];
    __shared__ int   s_cnt;

    int is64 = detect64(tar);
    int b   = blockIdx.x;
    int tid = threadIdx.x;   // 0..127
    if (tid == 0) {
        s_cnt = 0;
        out[b] = b2[0];
    }
    __syncthreads();

    long long ti = load_idx(tar, is64, b);
    long long tj = load_idx(tar, is64, (long long)N_PAIRS + b);

    if (tid < ROW_B4) {
        const uint4* rowi = reinterpret_cast<const uint4*>(&g_B[(size_t)ti * ROW_WB]);
        const uint4* rowj = reinterpret_cast<const uint4*>(&g_B[(size_t)tj * ROW_WB]);
        uint4 a = rowi[tid];
        uint4 q = rowj[tid];
        unsigned int m4[4] = {a.x & q.x, a.y & q.y, a.z & q.z, a.w & q.w};
#pragma unroll
        for (int w = 0; w < 4; w++) {
            unsigned int m = m4[w];
            while (m) {
                int bit = __ffs(m) - 1;
                int n = tid * 128 + w * 32 + bit;
                unsigned ua = 1u + hash_get((unsigned)(ti * 16384 + n));
                unsigned ub = 1u + hash_get((unsigned)(tj * 16384 + n));
                int idx = atomicAdd(&s_cnt, 1);
                if (idx < 512) {
                    s_n[idx] = n;
                    s_w[idx] = (float)(ua * ub);
                }
                m &= m - 1;
            }
        }
    }
    __syncthreads();

    int cnt = s_cnt < 512 ? s_cnt : 512;

    float xi = x[(size_t)ti * IN_CH + tid];
    float xj = x[(size_t)tj * IN_CH + tid];

    float acc = 0.f;
    for (int e = 0; e < cnt; e++)
        acc = fmaf(s_w[e], x[(size_t)s_n[e] * IN_CH + tid], acc);

    g_XS[(size_t)b * (2 * IN_CH) + tid]         = xi * xj;
    g_XS[(size_t)b * (2 * IN_CH) + IN_CH + tid] = acc;
}

// ---------------------------------------------------------------------------
// 3) Register-tiled fused GEMM:
//    C = XS[2048x256] * W1[256x512]; out[b] += sum_h relu(C+b1)*W2
// ---------------------------------------------------------------------------
#define BM 128
#define BN 64
#define BK 32
#define KTOT (2 * IN_CH)
#define NTILES (KTOT / BK)   // 8

__device__ __forceinline__ unsigned long long fma2(
    unsigned long long a, unsigned long long b, unsigned long long c) {
    unsigned long long d;
    asm("fma.rn.f32x2 %0, %1, %2, %3;" : "=l"(d) : "l"(a), "l"(b), "l"(c));
    return d;
}
__device__ __forceinline__ unsigned long long dup2(float w) {
    unsigned long long r;
    asm("mov.b64 %0, {%1, %1};" : "=l"(r) : "r"(__float_as_uint(w)));
    return r;
}

__global__ __launch_bounds__(256, 1)
void mlp_kernel(const float* __restrict__ W1, const float* __restrict__ b1,
                const float* __restrict__ W2, float* __restrict__ out) {
    __shared__ __align__(16) float s_x[BK][BM + 4];
    __shared__ __align__(16) float s_w[BK][BN];
    __shared__ float s_red[BM][17];

    int tid = threadIdx.x;
    int tx  = tid & 15;
    int ty  = tid >> 4;
    int b0  = (blockIdx.x & 15) * BM;
    int h0  = (blockIdx.x >> 4) * BN;

    float4 xr[4];
    float4 wr[2];
#pragma unroll
    for (int l = 0; l < 4; l++) {
        int fi = tid + l * 256;
        int p  = fi >> 3;
        int kc = fi & 7;
        xr[l] = *reinterpret_cast<const float4*>(&g_XS[(size_t)(b0 + p) * KTOT + kc * 4]);
    }
#pragma unroll
    for (int l = 0; l < 2; l++) {
        int fi = tid + l * 256;
        int kk = fi >> 4;
        int cc = (fi & 15) * 4;
        wr[l] = *reinterpret_cast<const float4*>(&W1[(size_t)kk * HIDDEN + h0 + cc]);
    }

    unsigned long long acc2[4][4];
#pragma unroll
    for (int i = 0; i < 4; i++)
#pragma unroll
        for (int j = 0; j < 4; j++) acc2[i][j] = 0ull;

    for (int t = 0; t < NTILES; t++) {
#pragma unroll
        for (int l = 0; l < 4; l++) {
            int fi = tid + l * 256;
            int p  = fi >> 3;
            int kc = fi & 7;
            s_x[kc * 4 + 0][p] = xr[l].x;
            s_x[kc * 4 + 1][p] = xr[l].y;
            s_x[kc * 4 + 2][p] = xr[l].z;
            s_x[kc * 4 + 3][p] = xr[l].w;
        }
#pragma unroll
        for (int l = 0; l < 2; l++) {
            int fi = tid + l * 256;
            int kk = fi >> 4;
            int cc = (fi & 15) * 4;
            *reinterpret_cast<float4*>(&s_w[kk][cc]) = wr[l];
        }
        __syncthreads();

        if (t + 1 < NTILES) {
            int k0 = (t + 1) * BK;
#pragma unroll
            for (int l = 0; l < 4; l++) {
                int fi = tid + l * 256;
                int p  = fi >> 3;
                int kc = fi & 7;
                xr[l] = *reinterpret_cast<const float4*>(
                    &g_XS[(size_t)(b0 + p) * KTOT + k0 + kc * 4]);
            }
#pragma unroll
            for (int l = 0; l < 2; l++) {
                int fi = tid + l * 256;
                int kk = fi >> 4;
                int cc = (fi & 15) * 4;
                wr[l] = *reinterpret_cast<const float4*>(
                    &W1[(size_t)(k0 + kk) * HIDDEN + h0 + cc]);
            }
        }

#pragma unroll 8
        for (int k = 0; k < BK; k++) {
            float4 wv = *reinterpret_cast<const float4*>(&s_w[k][tx * 4]);
            unsigned long long wd[4];
            wd[0] = dup2(wv.x); wd[1] = dup2(wv.y);
            wd[2] = dup2(wv.z); wd[3] = dup2(wv.w);
            ulonglong2 xa = *reinterpret_cast<const ulonglong2*>(&s_x[k][ty * 8]);
            ulonglong2 xb = *reinterpret_cast<const ulonglong2*>(&s_x[k][ty * 8 + 4]);
            unsigned long long xp[4] = {xa.x, xa.y, xb.x, xb.y};
#pragma unroll
            for (int pp = 0; pp < 4; pp++)
#pragma unroll
                for (int hh = 0; hh < 4; hh++)
                    acc2[pp][hh] = fma2(xp[pp], wd[hh], acc2[pp][hh]);
        }
        __syncthreads();
    }

    float4 b1v = *reinterpret_cast<const float4*>(&b1[h0 + tx * 4]);
    float4 w2v = *reinterpret_cast<const float4*>(&W2[h0 + tx * 4]);
    float bb[4] = {b1v.x, b1v.y, b1v.z, b1v.w};
    float ww[4] = {w2v.x, w2v.y, w2v.z, w2v.w};

    float pval[8];
#pragma unroll
    for (int pp = 0; pp < 4; pp++) {
        float lo = 0.f, hi = 0.f;
#pragma unroll
        for (int hh = 0; hh < 4; hh++) {
            union { unsigned long long u; float2 f; } cv;
            cv.u = acc2[pp][hh];
            lo += fmaxf(cv.f.x + bb[hh], 0.f) * ww[hh];
            hi += fmaxf(cv.f.y + bb[hh], 0.f) * ww[hh];
        }
        pval[pp * 2 + 0] = lo;
        pval[pp * 2 + 1] = hi;
    }

#pragma unroll
    for (int q = 0; q < 8; q++)
        s_red[ty * 8 + q][tx] = pval[q];
    __syncthreads();

    if (tid < BM) {
        float s = 0.f;
#pragma unroll
        for (int t = 0; t < 16; t++) s += s_red[tid][t];
        atomicAdd(&out[b0 + tid], s);
    }
}

// ---------------------------------------------------------------------------
// 4) Streaming clear: whole bitmap + hash (runs concurrent with mlp_kernel)
// ---------------------------------------------------------------------------
__global__ void clear_kernel() {
    size_t i = (size_t)blockIdx.x * blockDim.x + threadIdx.x;
    size_t nthreads = (size_t)gridDim.x * blockDim.x;

    uint4 z = make_uint4(0u, 0u, 0u, 0u);
    uint4* bp = reinterpret_cast<uint4*>(g_B);
    for (size_t w = i; w < BMP_U4; w += nthreads)
        bp[w] = z;

    if (i < HSIZE / 4) {
        reinterpret_cast<uint4*>(g_hk)[i] = z;
        reinterpret_cast<uint4*>(g_hc)[i] = z;
    }
}

// ---------------------------------------------------------------------------
// launch: fork clear onto a side stream, overlapping with mlp
// ---------------------------------------------------------------------------
extern "C" void kernel_launch(void* const* d_in, const int* in_sizes, int n_in,
                              void* d_out, int out_size) {
    const float* x   = (const float*)d_in[0];
    const void*  ei  = d_in[1];
    const void*  tar = d_in[2];
    const float* W1  = (const float*)d_in[3];
    const float* b1  = (const float*)d_in[4];
    const float* W2  = (const float*)d_in[5];
    const float* b2  = (const float*)d_in[6];
    float*       out = (float*)d_out;

    (void)in_sizes; (void)n_in; (void)out_size;

    static cudaStream_t s2 = []() {
        cudaStream_t s; cudaStreamCreateWithFlags(&s, cudaStreamNonBlocking); return s;
    }();
    static cudaEvent_t evFork = []() {
        cudaEvent_t e; cudaEventCreateWithFlags(&e, cudaEventDisableTiming); return e;
    }();
    static cudaEvent_t evJoin = []() {
        cudaEvent_t e; cudaEventCreateWithFlags(&e, cudaEventDisableTiming); return e;
    }();

    scatter_kernel<<<(N_EDGES + 255) / 256, 256>>>(ei);
    pairs_kernel<<<N_PAIRS, 128>>>(tar, x, b2, out);

    // fork: clear runs concurrently with mlp on side stream
    cudaEventRecord(evFork, 0);
    cudaStreamWaitEvent(s2, evFork, 0);
    clear_kernel<<<1184, 256, 0, s2>>>();
    cudaEventRecord(evJoin, s2);

    mlp_kernel<<<128, 256>>>(W1, b1, W2, out);

    // join: main stream completes only after clear finishes
    cudaStreamWaitEvent(0, evJoin, 0);
}

// round 9
// speedup vs baseline: 1.2162x; 1.2162x over previous
#include <cuda_runtime.h>
#include <stdint.h>

#define N_NODES 10000
#define N_EDGES 320000
#define N_PAIRS 2048
#define IN_CH   128
#define HIDDEN  512

#define ROW_WB  320
#define ROW_B4  80
#define BMP_U4  ((size_t)N_NODES * ROW_WB / 4)

#define HSIZE   32768
#define HMASK   (HSIZE - 1)

__device__ __align__(16) unsigned int g_B[(size_t)N_NODES * ROW_WB];
__device__ __align__(16) unsigned int g_hk[HSIZE];
__device__ __align__(16) unsigned int g_hc[HSIZE];
__device__ __align__(16) float g_XS[N_PAIRS * 2 * IN_CH];

// ---------------------------------------------------------------------------
__device__ __forceinline__ int detect64(const void* p) {
    const unsigned int* p32 = (const unsigned int*)p;
    int lane = threadIdx.x & 31;
    bool all0 = (p32[2 * lane + 1] | p32[2 * (lane + 32) + 1]) == 0u;
    return __ballot_sync(0xFFFFFFFFu, all0) == 0xFFFFFFFFu;
}
__device__ __forceinline__ long long load_idx(const void* p, int is64, long long j) {
    if (is64) return ((const long long*)p)[j];
    return (long long)((const int*)p)[j];
}

__device__ __forceinline__ void hash_add(unsigned key) {
    unsigned idx = (key * 2654435761u) & HMASK;
    for (;;) {
        unsigned cur = g_hk[idx];
        if (cur == key + 1u) { atomicAdd(&g_hc[idx], 1u); return; }
        if (cur == 0u) {
            unsigned old = atomicCAS(&g_hk[idx], 0u, key + 1u);
            if (old == 0u || old == key + 1u) { atomicAdd(&g_hc[idx], 1u); return; }
        }
        idx = (idx + 1u) & HMASK;
    }
}
__device__ __forceinline__ unsigned hash_get(unsigned key) {
    unsigned idx = (key * 2654435761u) & HMASK;
    for (;;) {
        unsigned cur = g_hk[idx];
        if (cur == 0u) return 0u;
        if (cur == key + 1u) return g_hc[idx];
        idx = (idx + 1u) & HMASK;
    }
}

// ---------------------------------------------------------------------------
// 1) Scatter
// ---------------------------------------------------------------------------
__global__ void scatter_kernel(const void* __restrict__ ei) {
    int is64 = detect64(ei);
    int e = blockIdx.x * blockDim.x + threadIdx.x;
    if (e >= N_EDGES) return;
    long long s = load_idx(ei, is64, e);
    long long d = load_idx(ei, is64, (long long)N_EDGES + e);
    unsigned bd = 1u << (d & 31);
    unsigned bs = 1u << (s & 31);
    unsigned o1 = atomicOr(&g_B[(size_t)s * ROW_WB + (size_t)(d >> 5)], bd);
    unsigned o2 = atomicOr(&g_B[(size_t)d * ROW_WB + (size_t)(s >> 5)], bs);
    if (o1 & bd) hash_add((unsigned)(s * 16384 + d));
    if (o2 & bs) hash_add((unsigned)(d * 16384 + s));
}

// ---------------------------------------------------------------------------
// 2) Pairs: intersect rows, build xs, init out[b] = b2[0]
// ---------------------------------------------------------------------------
__global__ void pairs_kernel(const void* __restrict__ tar,
                             const float* __restrict__ x,
                             const float* __restrict__ b2,
                             float* __restrict__ out) {
    __shared__ int   s_n[512];
    __shared__ float s_w[512];
    __shared__ int   s_cnt;

    int is64 = detect64(tar);
    int b   = blockIdx.x;
    int tid = threadIdx.x;
    if (tid == 0) {
        s_cnt = 0;
        out[b] = b2[0];
    }
    __syncthreads();

    long long ti = load_idx(tar, is64, b);
    long long tj = load_idx(tar, is64, (long long)N_PAIRS + b);

    if (tid < ROW_B4) {
        const uint4* rowi = reinterpret_cast<const uint4*>(&g_B[(size_t)ti * ROW_WB]);
        const uint4* rowj = reinterpret_cast<const uint4*>(&g_B[(size_t)tj * ROW_WB]);
        uint4 a = rowi[tid];
        uint4 q = rowj[tid];
        unsigned int m4[4] = {a.x & q.x, a.y & q.y, a.z & q.z, a.w & q.w};
#pragma unroll
        for (int w = 0; w < 4; w++) {
            unsigned int m = m4[w];
            while (m) {
                int bit = __ffs(m) - 1;
                int n = tid * 128 + w * 32 + bit;
                unsigned ua = 1u + hash_get((unsigned)(ti * 16384 + n));
                unsigned ub = 1u + hash_get((unsigned)(tj * 16384 + n));
                int idx = atomicAdd(&s_cnt, 1);
                if (idx < 512) {
                    s_n[idx] = n;
                    s_w[idx] = (float)(ua * ub);
                }
                m &= m - 1;
            }
        }
    }
    __syncthreads();

    int cnt = s_cnt < 512 ? s_cnt : 512;

    float xi = x[(size_t)ti * IN_CH + tid];
    float xj = x[(size_t)tj * IN_CH + tid];

    float acc = 0.f;
    for (int e = 0; e < cnt; e++)
        acc = fmaf(s_w[e], x[(size_t)s_n[e] * IN_CH + tid], acc);

    g_XS[(size_t)b * (2 * IN_CH) + tid]         = xi * xj;
    g_XS[(size_t)b * (2 * IN_CH) + IN_CH + tid] = acc;
}

// ---------------------------------------------------------------------------
// 3) Fused GEMM v3: BM=128 x BN=64, block k-split (kz=0: K[0,128), kz=1: K[128,256))
//    thread tile 8p x 8h via packed f32x2 FMA. Grid = 16 x 8 = 128 blocks.
// ---------------------------------------------------------------------------
#define BM 128
#define BN 64
#define KTOT (2 * IN_CH)
#define XPITCH (BM + 4)                       // 132 floats (528B, 16B-aligned)
#define SMEM_XBYTES (64 * XPITCH * 4)         // 33792
#define SMEM_MLP (SMEM_XBYTES + 64 * BN * 4)  // 33792 + 16384 = 50176

__device__ __forceinline__ unsigned long long fma2(
    unsigned long long a, unsigned long long b, unsigned long long c) {
    unsigned long long d;
    asm("fma.rn.f32x2 %0, %1, %2, %3;" : "=l"(d) : "l"(a), "l"(b), "l"(c));
    return d;
}
__device__ __forceinline__ unsigned long long dup2(float w) {
    unsigned long long r;
    asm("mov.b64 %0, {%1, %1};" : "=l"(r) : "r"(__float_as_uint(w)));
    return r;
}

__global__ __launch_bounds__(256, 1)
void mlp_kernel(const float* __restrict__ W1, const float* __restrict__ b1,
                const float* __restrict__ W2, float* __restrict__ out) {
    extern __shared__ unsigned char smbuf[];
    float (*s_x)[XPITCH] = reinterpret_cast<float (*)[XPITCH]>(smbuf);      // [64][132]
    float (*s_w)[BN]     = reinterpret_cast<float (*)[BN]>(smbuf + SMEM_XBYTES); // [64][64]
    unsigned long long* s_dump = reinterpret_cast<unsigned long long*>(smbuf);
    float* s_red = reinterpret_cast<float*>(smbuf + SMEM_XBYTES);

    int tid = threadIdx.x;
    int kz  = tid >> 7;          // k-half
    int r   = tid & 127;
    int ty  = r >> 3, tx = r & 7;
    int p0  = ty * 8;
    int b0  = (blockIdx.x & 15) * BM;
    int h0  = (blockIdx.x >> 4) * BN;
    int rot = tid & 3;

    float4 xr[8];
    float4 wr[4];

    // prefetch tile 0
#pragma unroll
    for (int l = 0; l < 8; l++) {
        int fi = tid + l * 256;
        int p = fi >> 4, c = fi & 15;
        int z = c >> 3, lc = c & 7;
        xr[l] = *(const float4*)&g_XS[(size_t)(b0 + p) * KTOT + z * 128 + lc * 4];
    }
#pragma unroll
    for (int l = 0; l < 4; l++) {
        int fi = tid + l * 256;
        int row = fi >> 4, c4 = fi & 15;
        int z = row >> 5, lr = row & 31;
        wr[l] = *(const float4*)&W1[(size_t)(z * 128 + lr) * HIDDEN + h0 + c4 * 4];
    }

    unsigned long long acc2[8][4];
#pragma unroll
    for (int i = 0; i < 8; i++)
#pragma unroll
        for (int j = 0; j < 4; j++) acc2[i][j] = 0ull;

    for (int t = 0; t < 4; t++) {
        // store prefetched tile (XS transposed with XOR-rotated row order)
#pragma unroll
        for (int l = 0; l < 8; l++) {
            int fi = tid + l * 256;
            int p = fi >> 4, c = fi & 15;
            int z = c >> 3, lc = c & 7;
            int row = z * 32 + lc * 4;
            float4 v = xr[l];
            float va0 = v.x, va1 = v.y, va2 = v.z, va3 = v.w;
            if (rot & 1) { float tq = va0; va0 = va1; va1 = tq; tq = va2; va2 = va3; va3 = tq; }
            if (rot & 2) { float tq = va0; va0 = va2; va2 = tq; tq = va1; va1 = va3; va3 = tq; }
            // va_q == original component (q ^ rot); store at row + (q ^ rot)
            s_x[row + (0 ^ rot)][p] = va0;
            s_x[row + (1 ^ rot)][p] = va1;
            s_x[row + (2 ^ rot)][p] = va2;
            s_x[row + (3 ^ rot)][p] = va3;
        }
#pragma unroll
        for (int l = 0; l < 4; l++) {
            int fi = tid + l * 256;
            int row = fi >> 4, c4 = fi & 15;
            *(float4*)&s_w[row][c4 * 4] = wr[l];
        }
        __syncthreads();

        // prefetch next tile
        if (t < 3) {
            int kb = (t + 1) * 32;
#pragma unroll
            for (int l = 0; l < 8; l++) {
                int fi = tid + l * 256;
                int p = fi >> 4, c = fi & 15;
                int z = c >> 3, lc = c & 7;
                xr[l] = *(const float4*)&g_XS[(size_t)(b0 + p) * KTOT + z * 128 + kb + lc * 4];
            }
#pragma unroll
            for (int l = 0; l < 4; l++) {
                int fi = tid + l * 256;
                int row = fi >> 4, c4 = fi & 15;
                int z = row >> 5, lr = row & 31;
                wr[l] = *(const float4*)&W1[(size_t)(z * 128 + kb + lr) * HIDDEN + h0 + c4 * 4];
            }
        }

        // compute: this thread's k-half rows
#pragma unroll 4
        for (int l = 0; l < 32; l++) {
            int row = kz * 32 + l;
            ulonglong2 xa = *(const ulonglong2*)&s_x[row][p0];
            ulonglong2 xb = *(const ulonglong2*)&s_x[row][p0 + 4];
            unsigned long long xp[4] = {xa.x, xa.y, xb.x, xb.y};
            float4 w0 = *(const float4*)&s_w[row][tx * 8];
            float4 w1 = *(const float4*)&s_w[row][tx * 8 + 4];
            float wf[8] = {w0.x, w0.y, w0.z, w0.w, w1.x, w1.y, w1.z, w1.w};
#pragma unroll
            for (int hh = 0; hh < 8; hh++) {
                unsigned long long wd = dup2(wf[hh]);
#pragma unroll
                for (int pp = 0; pp < 4; pp++)
                    acc2[hh][pp] = fma2(xp[pp], wd, acc2[hh][pp]);
            }
        }
        __syncthreads();
    }

    // combine k-halves through smem (aliases s_x, safe after final sync)
    if (kz == 1) {
        const unsigned long long* a = &acc2[0][0];
#pragma unroll
        for (int i = 0; i < 32; i++) s_dump[r * 32 + i] = a[i];
    }
    __syncthreads();

    if (kz == 0) {
        float4 b1a = *(const float4*)&b1[h0 + tx * 8];
        float4 b1b = *(const float4*)&b1[h0 + tx * 8 + 4];
        float4 w2a = *(const float4*)&W2[h0 + tx * 8];
        float4 w2b = *(const float4*)&W2[h0 + tx * 8 + 4];
        float bb[8] = {b1a.x, b1a.y, b1a.z, b1a.w, b1b.x, b1b.y, b1b.z, b1b.w};
        float ww[8] = {w2a.x, w2a.y, w2a.z, w2a.w, w2b.x, w2b.y, w2b.z, w2b.w};

        float pv[8];
#pragma unroll
        for (int q = 0; q < 8; q++) pv[q] = 0.f;

#pragma unroll
        for (int hh = 0; hh < 8; hh++) {
#pragma unroll
            for (int pp = 0; pp < 4; pp++) {
                union { unsigned long long u; float2 f; } c0, c1;
                c0.u = acc2[hh][pp];
                c1.u = s_dump[r * 32 + hh * 4 + pp];
                float lo = c0.f.x + c1.f.x;
                float hi = c0.f.y + c1.f.y;
                pv[2 * pp]     += fmaxf(lo + bb[hh], 0.f) * ww[hh];
                pv[2 * pp + 1] += fmaxf(hi + bb[hh], 0.f) * ww[hh];
            }
        }
#pragma unroll
        for (int q = 0; q < 8; q++) s_red[(p0 + q) * 8 + tx] = pv[q];
    }
    __syncthreads();

    if (tid < BM) {
        float s = 0.f;
#pragma unroll
        for (int q = 0; q < 8; q++) s += s_red[tid * 8 + q];
        atomicAdd(&out[b0 + tid], s);
    }
}

// ---------------------------------------------------------------------------
// 4) Streaming clear: whole bitmap + hash (serial, after mlp)
// ---------------------------------------------------------------------------
__global__ void clear_kernel() {
    size_t i = (size_t)blockIdx.x * blockDim.x + threadIdx.x;
    size_t nthreads = (size_t)gridDim.x * blockDim.x;

    uint4 z = make_uint4(0u, 0u, 0u, 0u);
    uint4* bp = reinterpret_cast<uint4*>(g_B);
    for (size_t w = i; w < BMP_U4; w += nthreads)
        bp[w] = z;

    if (i < HSIZE / 4) {
        reinterpret_cast<uint4*>(g_hk)[i] = z;
        reinterpret_cast<uint4*>(g_hc)[i] = z;
    }
}

// ---------------------------------------------------------------------------
// launch (single stream, serial)
// ---------------------------------------------------------------------------
extern "C" void kernel_launch(void* const* d_in, const int* in_sizes, int n_in,
                              void* d_out, int out_size) {
    const float* x   = (const float*)d_in[0];
    const void*  ei  = d_in[1];
    const void*  tar = d_in[2];
    const float* W1  = (const float*)d_in[3];
    const float* b1  = (const float*)d_in[4];
    const float* W2  = (const float*)d_in[5];
    const float* b2  = (const float*)d_in[6];
    float*       out = (float*)d_out;

    (void)in_sizes; (void)n_in; (void)out_size;

    static bool attr_ok = []() {
        cudaFuncSetAttribute(mlp_kernel,
                             cudaFuncAttributeMaxDynamicSharedMemorySize, SMEM_MLP);
        return true;
    }();
    (void)attr_ok;

    scatter_kernel<<<(N_EDGES + 255) / 256, 256>>>(ei);
    pairs_kernel<<<N_PAIRS, 128>>>(tar, x, b2, out);
    mlp_kernel<<<128, 256, SMEM_MLP>>>(W1, b1, W2, out);
    clear_kernel<<<1184, 256>>>();
}